// round 15
// baseline (speedup 1.0000x reference)
#include <cuda_runtime.h>
#include <math.h>
#include <stdint.h>

#define NN 50000
#define EE 500000
#define CLAMPV 5.0f

// ---------------- scratch ----------------------------------------------------
__device__ float g_Qh[NN * 128];
__device__ float g_Kh[NN * 128];
__device__ float g_Vh[NN * 128];
__device__ float g_denom[NN * 8];
__device__ float g_rowV[NN * 128];   // unnormalized sum conn*ex
__device__ float g_accV[NN * 128];   // unnormalized sum Vh[src]*ex

// ---------------- helpers ----------------------------------------------------
__device__ __forceinline__ void red_add_v4(float* addr, float a, float b, float c, float d) {
    asm volatile("red.global.add.v4.f32 [%0], {%1,%2,%3,%4};"
                 :: "l"(addr), "f"(a), "f"(b), "f"(c), "f"(d) : "memory");
}

// ---------------- node GEMM: 128(M) x 128(N), 8x8 microtile -------------------
// which==0 additionally zeroes the aggregation scratch for its row range.
__global__ __launch_bounds__(256) void node_gemm(
    const float* __restrict__ x,
    const float* __restrict__ WQ, const float* __restrict__ bQ,
    const float* __restrict__ WK, const float* __restrict__ bK,
    const float* __restrict__ WV, const float* __restrict__ bV,
    float* __restrict__ d_out)
{
    const int which = blockIdx.y;
    const float* W    = (which == 0) ? WQ : (which == 1) ? WK : WV;
    const float* bias = (which == 0) ? bQ : (which == 1) ? bK : bV;
    float* out        = (which == 0) ? g_Qh : (which == 1) ? g_Kh : g_Vh;

    __shared__ float As[128 * 16];
    __shared__ float Bs[16 * 128];

    const int tid = threadIdx.x;
    const int tx = tid & 15, ty = tid >> 4;
    const int m0 = blockIdx.x * 128;

    if (which == 0) {
        const float4 z4 = make_float4(0.f, 0.f, 0.f, 0.f);
        for (int i = tid; i < 128 * 32; i += 256) {
            int m = m0 + (i >> 5);
            if (m < NN) {
                ((float4*)g_accV)[(size_t)m * 32 + (i & 31)] = z4;
                ((float4*)g_rowV)[(size_t)m * 32 + (i & 31)] = z4;
            }
        }
        for (int i = tid; i < 128 * 8; i += 256) {
            int m = m0 + (i >> 3);
            if (m < NN) g_denom[m * 8 + (i & 7)] = 0.f;
        }
    }

    const int ar = tid >> 1;            // 0..127
    const int ac = (tid & 1) * 8;       // 0 or 8
    const int brow = tid >> 4;          // 0..15
    const int bcol = (tid & 15) * 8;    // 0..120
    const int mrow = m0 + ar;

    float acc[8][8];
    #pragma unroll
    for (int i = 0; i < 8; i++)
        #pragma unroll
        for (int j = 0; j < 8; j++) acc[i][j] = 0.f;

    for (int k0 = 0; k0 < 128; k0 += 16) {
        float4 a0 = make_float4(0.f, 0.f, 0.f, 0.f);
        float4 a1 = make_float4(0.f, 0.f, 0.f, 0.f);
        if (mrow < NN) {
            a0 = *(const float4*)&x[(size_t)mrow * 128 + k0 + ac];
            a1 = *(const float4*)&x[(size_t)mrow * 128 + k0 + ac + 4];
        }
        *(float4*)&As[ar * 16 + ac]     = a0;
        *(float4*)&As[ar * 16 + ac + 4] = a1;
        *(float4*)&Bs[brow * 128 + bcol]     = *(const float4*)&W[(size_t)(k0 + brow) * 128 + bcol];
        *(float4*)&Bs[brow * 128 + bcol + 4] = *(const float4*)&W[(size_t)(k0 + brow) * 128 + bcol + 4];
        __syncthreads();
        #pragma unroll
        for (int k = 0; k < 16; k++) {
            float a[8], b[8];
            #pragma unroll
            for (int i = 0; i < 8; i++) a[i] = As[(ty * 8 + i) * 16 + k];
            #pragma unroll
            for (int j = 0; j < 8; j++) b[j] = Bs[k * 128 + tx * 8 + j];
            #pragma unroll
            for (int i = 0; i < 8; i++)
                #pragma unroll
                for (int j = 0; j < 8; j++)
                    acc[i][j] = fmaf(a[i], b[j], acc[i][j]);
        }
        __syncthreads();
    }

    #pragma unroll
    for (int i = 0; i < 8; i++) {
        int m = m0 + ty * 8 + i;
        if (m >= NN) continue;
        #pragma unroll
        for (int j = 0; j < 8; j++) {
            int c = tx * 8 + j;
            float v = acc[i][j] + bias[c];
            out[(size_t)m * 128 + c] = v;
            if (which == 0) d_out[(size_t)m * 128 + c] = v;
        }
    }
}

// ---------------- edge GEMM fp32: A-resident + B double-buffered --------------
// 64(M) x 256(N) CTA tile, 512 threads, 4x8 microtile (32 acc regs/thread,
// <=64 regs -> 2 CTA/SM = 32 warps/SM for latency hiding).
// A tile [64][128] (32KB) in smem once; B double-buffered 2x16KB; one sync
// per chunk. Epilogue identical to round-14 (conn/score/exp + fused
// unnormalized aggregation), rescaled to 512 threads.
// Smem floats: As[64][128] @ [0,8192); BsB[2][16][256] @ [8192,16384);
// Ex[64][256] @ [0,16384) aliases both after compute; AwS @ [16384,16512).
__global__ __launch_bounds__(512, 2) void edge_gemm_f32(
    const float* __restrict__ ea,
    const float* __restrict__ WE, const float* __restrict__ bE,
    const int* __restrict__ edge_index,
    const float* __restrict__ Aw,
    float* __restrict__ d_out)
{
    extern __shared__ float sm[];
    float* As  = sm;            // [64][128]
    float* BsB = sm + 8192;     // [2][16][256]
    float* Ex  = sm;            // [64][256] (aliases As+BsB after compute)
    float* AwS = sm + 16384;    // [128]

    const int tid = threadIdx.x;
    const int tx = tid & 31, ty = tid >> 5;   // 32 x 16 thread grid
    const int m0 = blockIdx.x * 64;

    if (tid < 128) AwS[tid] = Aw[tid];

    // ---- prologue: load A tile once + B chunk 0 ----
    {
        const int arow = tid >> 3;                       // 0..63
        const size_t asrc = (size_t)((m0 + arow < EE) ? (m0 + arow) : (EE - 1)) * 128;
        #pragma unroll
        for (int it = 0; it < 4; it++) {
            int c4 = (tid & 7) + 8 * it;                 // float4 position 0..31
            *(float4*)&As[arow * 128 + c4 * 4] = *(const float4*)&ea[asrc + c4 * 4];
        }
        const int brow = tid >> 5;                       // 0..15
        #pragma unroll
        for (int it = 0; it < 2; it++) {
            int c4 = (tid & 31) + 32 * it;               // float4 position 0..63
            *(float4*)&BsB[brow * 256 + c4 * 4] = *(const float4*)&WE[(size_t)brow * 256 + c4 * 4];
        }
    }
    __syncthreads();

    float acc[4][8];
    #pragma unroll
    for (int i = 0; i < 4; i++)
        #pragma unroll
        for (int j = 0; j < 8; j++) acc[i][j] = 0.f;

    for (int ch = 0; ch < 8; ch++) {
        const float* Bs = BsB + (ch & 1) * 4096;
        if (ch < 7) {   // stage next B chunk into the other buffer (L2-hot)
            float* Bn = BsB + ((ch & 1) ^ 1) * 4096;
            const int kn = (ch + 1) * 16;
            const int brow = tid >> 5;
            #pragma unroll
            for (int it = 0; it < 2; it++) {
                int c4 = (tid & 31) + 32 * it;
                *(float4*)&Bn[brow * 256 + c4 * 4] =
                    *(const float4*)&WE[(size_t)(kn + brow) * 256 + c4 * 4];
            }
        }
        const int kb = ch * 16;
        #pragma unroll
        for (int kk = 0; kk < 16; kk++) {
            const int k = kb + kk;
            float a[4];
            #pragma unroll
            for (int i = 0; i < 4; i++) a[i] = As[(ty * 4 + i) * 128 + k];  // broadcast
            float4 b0 = *(const float4*)&Bs[kk * 256 + tx * 8];
            float4 b1 = *(const float4*)&Bs[kk * 256 + tx * 8 + 4];
            const float b[8] = {b0.x, b0.y, b0.z, b0.w, b1.x, b1.y, b1.z, b1.w};
            #pragma unroll
            for (int i = 0; i < 4; i++)
                #pragma unroll
                for (int j = 0; j < 8; j++)
                    acc[i][j] = fmaf(a[i], b[j], acc[i][j]);
        }
        __syncthreads();   // buf(ch^1) fully written & buf(ch) fully read
    }

    // ---- stash Ex (+bias) ----
    #pragma unroll
    for (int i = 0; i < 4; i++) {
        int r = ty * 4 + i;
        #pragma unroll
        for (int j = 0; j < 8; j++) {
            int c = tx * 8 + j;
            Ex[r * 256 + c] = acc[i][j] + bE[c];
        }
    }
    __syncthreads();

    float* connOut = d_out + (size_t)NN * 128;

    // ---- conn: 64 edges * 8 heads * 16 dims = 8192 values, 16 per thread ----
    for (int idx = tid; idx < 64 * 128; idx += 512) {
        int el  = idx >> 7;
        int rem = idx & 127;
        int gg  = rem >> 4;     // head 0..7
        int d   = rem & 15;
        int e   = m0 + el;
        float x1 = Ex[el * 256 + gg * 32 + d];
        float x2 = Ex[el * 256 + gg * 32 + 16 + d];
        float s2 = x1 * x2;
        float sc2 = copysignf(sqrtf(fabsf(s2)), s2);
        if (e < EE) {
            int src = edge_index[e];
            int dst = edge_index[EE + e];
            float conn = g_Kh[(size_t)src * 128 + gg * 16 + d]
                       + g_Qh[(size_t)dst * 128 + gg * 16 + d] + sc2;
            connOut[(size_t)e * 128 + gg * 16 + d] = conn;
            Ex[el * 256 + gg * 32 + d] = conn;
        }
    }
    __syncthreads();

    // ---- score + fused aggregation per (edge, head): 512 tasks, 1/thread ----
    {
        int el = tid >> 3;
        int gg = tid & 7;
        int e  = m0 + el;
        if (e < EE) {
            const float* cx = &Ex[el * 256 + gg * 32];
            float s = 0.f;
            #pragma unroll
            for (int d = 0; d < 16; d++)
                s = fmaf(cx[d], AwS[d * 8 + gg], s);
            s = fminf(fmaxf(s, -CLAMPV), CLAMPV);
            float eev = expf(s);
            int src = edge_index[e];
            int dst = edge_index[EE + e];
            atomicAdd(&g_denom[dst * 8 + gg], eev);
            const float4* vv4 = (const float4*)&g_Vh[(size_t)src * 128 + gg * 16];
            float* av = &g_accV[(size_t)dst * 128 + gg * 16];
            float* rv = &g_rowV[(size_t)dst * 128 + gg * 16];
            #pragma unroll
            for (int q = 0; q < 4; q++) {
                float4 v = vv4[q];
                red_add_v4(av + q * 4, v.x * eev, v.y * eev, v.z * eev, v.w * eev);
                red_add_v4(rv + q * 4,
                           cx[q * 4 + 0] * eev, cx[q * 4 + 1] * eev,
                           cx[q * 4 + 2] * eev, cx[q * 4 + 3] * eev);
            }
        }
    }
}

// ---------------- finalize: Vo = Qh + accV/den + (rowV/den)@VeRow -------------
__global__ __launch_bounds__(128) void finalize(
    const float* __restrict__ VeRow,
    float* __restrict__ d_out)
{
    __shared__ float Vs[2048];
    const int tid = threadIdx.x;
    for (int i = tid; i < 2048; i += 128) Vs[i] = VeRow[i];
    __syncthreads();

    const int h = tid >> 4, c = tid & 15;
    const int n0 = blockIdx.x * 8;
    const int nend = (n0 + 8 < NN) ? n0 + 8 : NN;
    for (int n = n0; n < nend; n++) {
        float den = g_denom[n * 8 + h] + 1e-16f;
        float acc = 0.f;
        #pragma unroll
        for (int d = 0; d < 16; d++)
            acc = fmaf(g_rowV[(size_t)n * 128 + h * 16 + d], Vs[d * 128 + h * 16 + c], acc);
        float msg = g_accV[(size_t)n * 128 + h * 16 + c];
        d_out[(size_t)n * 128 + h * 16 + c] += (msg + acc) / den;
    }
}

// ---------------- launch ------------------------------------------------------
#define EDGE_SM ((64 * 256 + 128) * 4)   // 66048 bytes

extern "C" void kernel_launch(void* const* d_in, const int* in_sizes, int n_in,
                              void* d_out, int out_size)
{
    const float* x    = (const float*)d_in[0];
    const float* ea   = (const float*)d_in[1];
    const int*   eidx = (const int*)  d_in[2];
    const float* WQ   = (const float*)d_in[3];
    const float* bQ   = (const float*)d_in[4];
    const float* WK   = (const float*)d_in[5];
    const float* bK   = (const float*)d_in[6];
    const float* WE   = (const float*)d_in[7];
    const float* bE   = (const float*)d_in[8];
    const float* WV   = (const float*)d_in[9];
    const float* bV   = (const float*)d_in[10];
    const float* Aw   = (const float*)d_in[11];
    const float* VeRow= (const float*)d_in[12];
    float* out = (float*)d_out;

    static bool attr_set = false;
    if (!attr_set) {
        cudaFuncSetAttribute(edge_gemm_f32,
                             cudaFuncAttributeMaxDynamicSharedMemorySize, EDGE_SM);
        attr_set = true;
    }

    dim3 gn((NN + 127) / 128, 3);
    node_gemm<<<gn, 256>>>(x, WQ, bQ, WK, bK, WV, bV, out);

    edge_gemm_f32<<<(EE + 63) / 64, 512, EDGE_SM>>>(ea, WE, bE, eidx, Aw, out);

    finalize<<<(NN + 7) / 8, 128>>>(VeRow, out);
}

// round 16
// speedup vs baseline: 1.1016x; 1.1016x over previous
#include <cuda_runtime.h>
#include <math.h>
#include <stdint.h>

#define NN 50000
#define EE 500000
#define CLAMPV 5.0f

// ---------------- scratch ----------------------------------------------------
__device__ float g_Qh[NN * 128];
__device__ float g_Kh[NN * 128];
__device__ float g_Vh[NN * 128];
__device__ float g_denom[NN * 8];
__device__ float g_rowV[NN * 128];   // unnormalized sum conn*ex
__device__ float g_accV[NN * 128];   // unnormalized sum Vh[src]*ex

// ---------------- helpers ----------------------------------------------------
__device__ __forceinline__ void red_add_v4(float* addr, float a, float b, float c, float d) {
    asm volatile("red.global.add.v4.f32 [%0], {%1,%2,%3,%4};"
                 :: "l"(addr), "f"(a), "f"(b), "f"(c), "f"(d) : "memory");
}

// ---------------- node GEMM: 128(M) x 128(N), 8x8 microtile, A transposed -----
// which==0 additionally zeroes the aggregation scratch for its row range.
__global__ __launch_bounds__(256) void node_gemm(
    const float* __restrict__ x,
    const float* __restrict__ WQ, const float* __restrict__ bQ,
    const float* __restrict__ WK, const float* __restrict__ bK,
    const float* __restrict__ WV, const float* __restrict__ bV,
    float* __restrict__ d_out)
{
    const int which = blockIdx.y;
    const float* W    = (which == 0) ? WQ : (which == 1) ? WK : WV;
    const float* bias = (which == 0) ? bQ : (which == 1) ? bK : bV;
    float* out        = (which == 0) ? g_Qh : (which == 1) ? g_Kh : g_Vh;

    __shared__ float AsT[16 * 128];   // [k][row] transposed
    __shared__ float Bs[16 * 128];

    const int tid = threadIdx.x;
    const int tx = tid & 15, ty = tid >> 4;
    const int m0 = blockIdx.x * 128;

    if (which == 0) {
        const float4 z4 = make_float4(0.f, 0.f, 0.f, 0.f);
        for (int i = tid; i < 128 * 32; i += 256) {
            int m = m0 + (i >> 5);
            if (m < NN) {
                ((float4*)g_accV)[(size_t)m * 32 + (i & 31)] = z4;
                ((float4*)g_rowV)[(size_t)m * 32 + (i & 31)] = z4;
            }
        }
        for (int i = tid; i < 128 * 8; i += 256) {
            int m = m0 + (i >> 3);
            if (m < NN) g_denom[m * 8 + (i & 7)] = 0.f;
        }
    }

    const int ar = tid >> 1;            // 0..127
    const int ac = (tid & 1) * 8;       // 0 or 8
    const int brow = tid >> 4;          // 0..15
    const int bcol = (tid & 15) * 8;    // 0..120
    const int mrow = m0 + ar;

    float acc[8][8];
    #pragma unroll
    for (int i = 0; i < 8; i++)
        #pragma unroll
        for (int j = 0; j < 8; j++) acc[i][j] = 0.f;

    for (int k0 = 0; k0 < 128; k0 += 16) {
        float4 a0 = make_float4(0.f, 0.f, 0.f, 0.f);
        float4 a1 = make_float4(0.f, 0.f, 0.f, 0.f);
        if (mrow < NN) {
            a0 = *(const float4*)&x[(size_t)mrow * 128 + k0 + ac];
            a1 = *(const float4*)&x[(size_t)mrow * 128 + k0 + ac + 4];
        }
        AsT[(ac + 0) * 128 + ar] = a0.x;
        AsT[(ac + 1) * 128 + ar] = a0.y;
        AsT[(ac + 2) * 128 + ar] = a0.z;
        AsT[(ac + 3) * 128 + ar] = a0.w;
        AsT[(ac + 4) * 128 + ar] = a1.x;
        AsT[(ac + 5) * 128 + ar] = a1.y;
        AsT[(ac + 6) * 128 + ar] = a1.z;
        AsT[(ac + 7) * 128 + ar] = a1.w;
        *(float4*)&Bs[brow * 128 + bcol]     = *(const float4*)&W[(size_t)(k0 + brow) * 128 + bcol];
        *(float4*)&Bs[brow * 128 + bcol + 4] = *(const float4*)&W[(size_t)(k0 + brow) * 128 + bcol + 4];
        __syncthreads();
        #pragma unroll
        for (int k = 0; k < 16; k++) {
            float4 av0 = *(const float4*)&AsT[k * 128 + ty * 8];       // broadcast
            float4 av1 = *(const float4*)&AsT[k * 128 + ty * 8 + 4];
            float4 bv0 = *(const float4*)&Bs[k * 128 + tx * 8];
            float4 bv1 = *(const float4*)&Bs[k * 128 + tx * 8 + 4];
            const float a[8] = {av0.x, av0.y, av0.z, av0.w, av1.x, av1.y, av1.z, av1.w};
            const float b[8] = {bv0.x, bv0.y, bv0.z, bv0.w, bv1.x, bv1.y, bv1.z, bv1.w};
            #pragma unroll
            for (int i = 0; i < 8; i++)
                #pragma unroll
                for (int j = 0; j < 8; j++)
                    acc[i][j] = fmaf(a[i], b[j], acc[i][j]);
        }
        __syncthreads();
    }

    #pragma unroll
    for (int i = 0; i < 8; i++) {
        int m = m0 + ty * 8 + i;
        if (m >= NN) continue;
        #pragma unroll
        for (int j = 0; j < 8; j++) {
            int c = tx * 8 + j;
            float v = acc[i][j] + bias[c];
            out[(size_t)m * 128 + c] = v;
            if (which == 0) d_out[(size_t)m * 128 + c] = v;
        }
    }
}

// ---------------- edge GEMM fp32: A-resident (transposed) + B dbl-buffered ----
// 64(M) x 256(N), 8x8 microtile, 256 threads (round-14 proven structure).
// A stored TRANSPOSED AsT[128][64] so the 8 A-fragment reads per k-step are
// 2 broadcast LDS.128 instead of 8 scalar LDS -> FFMA issue share 86%->94%.
// Smem floats: AsT[128][64] @ [0,8192); BsB[2][16][256] @ [8192,16384);
// Ex[64][256] @ [0,16384) aliases both after compute; AwS @ [16384,16512).
__global__ __launch_bounds__(256) void edge_gemm_f32(
    const float* __restrict__ ea,
    const float* __restrict__ WE, const float* __restrict__ bE,
    const int* __restrict__ edge_index,
    const float* __restrict__ Aw,
    float* __restrict__ d_out)
{
    extern __shared__ float sm[];
    float* AsT = sm;            // [128][64]  (k, row)
    float* BsB = sm + 8192;     // [2][16][256]
    float* Ex  = sm;            // [64][256] (aliases AsT+BsB after compute)
    float* AwS = sm + 16384;    // [128]

    const int tid = threadIdx.x;
    const int tx = tid & 31, ty = tid >> 5;   // 32 x 8 thread grid
    const int m0 = blockIdx.x * 64;

    if (tid < 128) AwS[tid] = Aw[tid];

    // ---- prologue: load A tile once (transposing) + B chunk 0 ----
    {
        const int arow = tid >> 2;                       // 0..63
        const size_t asrc = (size_t)((m0 + arow < EE) ? (m0 + arow) : (EE - 1)) * 128;
        #pragma unroll
        for (int it = 0; it < 8; it++) {
            int c4 = (tid & 3) + 4 * it;                 // float4 position 0..31
            float4 v = *(const float4*)&ea[asrc + c4 * 4];
            AsT[(c4 * 4 + 0) * 64 + arow] = v.x;
            AsT[(c4 * 4 + 1) * 64 + arow] = v.y;
            AsT[(c4 * 4 + 2) * 64 + arow] = v.z;
            AsT[(c4 * 4 + 3) * 64 + arow] = v.w;
        }
        const int brow = tid >> 4;                       // 0..15
        #pragma unroll
        for (int it = 0; it < 4; it++) {
            int c4 = (tid & 15) + 16 * it;               // float4 position 0..63
            *(float4*)&BsB[brow * 256 + c4 * 4] = *(const float4*)&WE[(size_t)brow * 256 + c4 * 4];
        }
    }
    __syncthreads();

    float acc[8][8];
    #pragma unroll
    for (int i = 0; i < 8; i++)
        #pragma unroll
        for (int j = 0; j < 8; j++) acc[i][j] = 0.f;

    for (int ch = 0; ch < 8; ch++) {
        const float* Bs = BsB + (ch & 1) * 4096;
        if (ch < 7) {   // stage next B chunk into the other buffer (L2-hot)
            float* Bn = BsB + ((ch & 1) ^ 1) * 4096;
            const int kn = (ch + 1) * 16;
            const int brow = tid >> 4;
            #pragma unroll
            for (int it = 0; it < 4; it++) {
                int c4 = (tid & 15) + 16 * it;
                *(float4*)&Bn[brow * 256 + c4 * 4] =
                    *(const float4*)&WE[(size_t)(kn + brow) * 256 + c4 * 4];
            }
        }
        const int kb = ch * 16;
        #pragma unroll
        for (int kk = 0; kk < 16; kk++) {
            const int k = kb + kk;
            float4 av0 = *(const float4*)&AsT[k * 64 + ty * 8];      // broadcast
            float4 av1 = *(const float4*)&AsT[k * 64 + ty * 8 + 4];
            float4 bv0 = *(const float4*)&Bs[kk * 256 + tx * 8];
            float4 bv1 = *(const float4*)&Bs[kk * 256 + tx * 8 + 4];
            const float a[8] = {av0.x, av0.y, av0.z, av0.w, av1.x, av1.y, av1.z, av1.w};
            const float b[8] = {bv0.x, bv0.y, bv0.z, bv0.w, bv1.x, bv1.y, bv1.z, bv1.w};
            #pragma unroll
            for (int i = 0; i < 8; i++)
                #pragma unroll
                for (int j = 0; j < 8; j++)
                    acc[i][j] = fmaf(a[i], b[j], acc[i][j]);
        }
        __syncthreads();   // buf(ch^1) fully written & buf(ch) fully read
    }

    // ---- stash Ex (+bias) ----
    #pragma unroll
    for (int i = 0; i < 8; i++) {
        int r = ty * 8 + i;
        #pragma unroll
        for (int j = 0; j < 8; j++) {
            int c = tx * 8 + j;
            Ex[r * 256 + c] = acc[i][j] + bE[c];
        }
    }
    __syncthreads();

    float* connOut = d_out + (size_t)NN * 128;

    // ---- conn: 64 edges * 8 heads * 16 dims = 8192 values, 32 per thread ----
    for (int idx = tid; idx < 64 * 128; idx += 256) {
        int el  = idx >> 7;
        int rem = idx & 127;
        int gg  = rem >> 4;     // head 0..7
        int d   = rem & 15;
        int e   = m0 + el;
        float x1 = Ex[el * 256 + gg * 32 + d];
        float x2 = Ex[el * 256 + gg * 32 + 16 + d];
        float s2 = x1 * x2;
        float sc2 = copysignf(sqrtf(fabsf(s2)), s2);
        if (e < EE) {
            int src = edge_index[e];
            int dst = edge_index[EE + e];
            float conn = g_Kh[(size_t)src * 128 + gg * 16 + d]
                       + g_Qh[(size_t)dst * 128 + gg * 16 + d] + sc2;
            connOut[(size_t)e * 128 + gg * 16 + d] = conn;
            Ex[el * 256 + gg * 32 + d] = conn;
        }
    }
    __syncthreads();

    // ---- score + fused aggregation per (edge, head): 512 tasks ----
    #pragma unroll
    for (int it = 0; it < 2; it++) {
        int t  = tid + it * 256;
        int el = t >> 3;
        int gg = t & 7;
        int e  = m0 + el;
        if (e < EE) {
            const float* cx = &Ex[el * 256 + gg * 32];
            float s = 0.f;
            #pragma unroll
            for (int d = 0; d < 16; d++)
                s = fmaf(cx[d], AwS[d * 8 + gg], s);
            s = fminf(fmaxf(s, -CLAMPV), CLAMPV);
            float eev = expf(s);
            int src = edge_index[e];
            int dst = edge_index[EE + e];
            atomicAdd(&g_denom[dst * 8 + gg], eev);
            const float4* vv4 = (const float4*)&g_Vh[(size_t)src * 128 + gg * 16];
            float* av = &g_accV[(size_t)dst * 128 + gg * 16];
            float* rv = &g_rowV[(size_t)dst * 128 + gg * 16];
            #pragma unroll
            for (int q = 0; q < 4; q++) {
                float4 v = vv4[q];
                red_add_v4(av + q * 4, v.x * eev, v.y * eev, v.z * eev, v.w * eev);
                red_add_v4(rv + q * 4,
                           cx[q * 4 + 0] * eev, cx[q * 4 + 1] * eev,
                           cx[q * 4 + 2] * eev, cx[q * 4 + 3] * eev);
            }
        }
    }
}

// ---------------- finalize: Vo = Qh + accV/den + (rowV/den)@VeRow -------------
__global__ __launch_bounds__(128) void finalize(
    const float* __restrict__ VeRow,
    float* __restrict__ d_out)
{
    __shared__ float Vs[2048];
    const int tid = threadIdx.x;
    for (int i = tid; i < 2048; i += 128) Vs[i] = VeRow[i];
    __syncthreads();

    const int h = tid >> 4, c = tid & 15;
    const int n0 = blockIdx.x * 8;
    const int nend = (n0 + 8 < NN) ? n0 + 8 : NN;
    for (int n = n0; n < nend; n++) {
        float den = g_denom[n * 8 + h] + 1e-16f;
        float acc = 0.f;
        #pragma unroll
        for (int d = 0; d < 16; d++)
            acc = fmaf(g_rowV[(size_t)n * 128 + h * 16 + d], Vs[d * 128 + h * 16 + c], acc);
        float msg = g_accV[(size_t)n * 128 + h * 16 + c];
        d_out[(size_t)n * 128 + h * 16 + c] += (msg + acc) / den;
    }
}

// ---------------- launch ------------------------------------------------------
#define EDGE_SM ((64 * 256 + 128) * 4)   // 66048 bytes

extern "C" void kernel_launch(void* const* d_in, const int* in_sizes, int n_in,
                              void* d_out, int out_size)
{
    const float* x    = (const float*)d_in[0];
    const float* ea   = (const float*)d_in[1];
    const int*   eidx = (const int*)  d_in[2];
    const float* WQ   = (const float*)d_in[3];
    const float* bQ   = (const float*)d_in[4];
    const float* WK   = (const float*)d_in[5];
    const float* bK   = (const float*)d_in[6];
    const float* WE   = (const float*)d_in[7];
    const float* bE   = (const float*)d_in[8];
    const float* WV   = (const float*)d_in[9];
    const float* bV   = (const float*)d_in[10];
    const float* Aw   = (const float*)d_in[11];
    const float* VeRow= (const float*)d_in[12];
    float* out = (float*)d_out;

    static bool attr_set = false;
    if (!attr_set) {
        cudaFuncSetAttribute(edge_gemm_f32,
                             cudaFuncAttributeMaxDynamicSharedMemorySize, EDGE_SM);
        attr_set = true;
    }

    dim3 gn((NN + 127) / 128, 3);
    node_gemm<<<gn, 256>>>(x, WQ, bQ, WK, bK, WV, bV, out);

    edge_gemm_f32<<<(EE + 63) / 64, 256, EDGE_SM>>>(ea, WE, bE, eidx, Aw, out);

    finalize<<<(NN + 7) / 8, 128>>>(VeRow, out);
}